// round 12
// baseline (speedup 1.0000x reference)
#include <cuda_runtime.h>
#include <cstdint>

// VecLeadingZeroDetector108: for each row of 108 MSB-first bits (float 0/1),
// output the 7-bit MSB-first binary of the index of the first 1 (108 if none).
//
// Design: warp-cooperative early exit, 16 rows/warp (MLP=16 phase 0).
// Lane-reversed element mapping: lane l handles element c*32 + (31-l), so the
// first set element index = c*32 + __clz(ballot)  (no BREV/FFS chain).
// Row results live in lane j's register (shfl at output), no 64-bit packing.

#define N_BITS 108
#define N_OUT 7
#define R 16   // rows per warp

__global__ __launch_bounds__(256, 8)
void lzd108_kernel(const float* __restrict__ X, float* __restrict__ out, int nrows)
{
    const unsigned gwarp = (blockIdx.x * blockDim.x + threadIdx.x) >> 5;
    const unsigned lane  = threadIdx.x & 31;
    const unsigned rlane = lane ^ 31u;        // reversed lane -> element offset

    const unsigned base_row = gwarp * R;
    if (base_row >= (unsigned)nrows) return;

    const bool full = (base_row + R) <= (unsigned)nrows;    // warp-uniform
    const unsigned rowoff = base_row * N_BITS + rlane;      // 32-bit element offset

    float v[R];
    unsigned pending = 0;       // warp-uniform bitmask of unresolved rows
    int myidx = N_BITS;         // lane j holds result for row j (j < R)

    // ---- phase 0: elements [0,32) of every row, 16 loads back-to-back ----
    if (full) {
        #pragma unroll
        for (int j = 0; j < R; j++)
            v[j] = __ldcs(X + rowoff + j * N_BITS);
    } else {
        #pragma unroll
        for (int j = 0; j < R; j++)
            v[j] = (base_row + j < (unsigned)nrows) ? __ldcs(X + rowoff + j * N_BITS) : 1.0f;
    }
    #pragma unroll
    for (int j = 0; j < R; j++) {
        const unsigned m = __ballot_sync(0xffffffffu, v[j] != 0.0f);
        if (m) {
            // lowest element index among set lanes = __clz(m) (reversed mapping)
            if (lane == (unsigned)j) myidx = __clz(m);
        } else {
            pending |= (1u << j);
        }
    }

    // ---- phases 1..3: only pending rows; all loads first (MLP), then ballots ----
    #pragma unroll
    for (int c = 1; c < 4; c++) {
        if (!pending) break;                       // warp-uniform
        const bool in_row = (c * 32 + rlane) < N_BITS;   // only binds at c==3
        #pragma unroll
        for (int j = 0; j < R; j++) {
            if (pending & (1u << j))
                v[j] = in_row ? __ldcs(X + rowoff + j * N_BITS + c * 32) : 0.0f;
        }
        #pragma unroll
        for (int j = 0; j < R; j++) {
            if (pending & (1u << j)) {
                const unsigned m = __ballot_sync(0xffffffffu, v[j] != 0.0f);
                if (m) {
                    if (lane == (unsigned)j) myidx = c * 32 + __clz(m);
                    pending &= ~(1u << j);
                }
            }
        }
    }

    // ---- write 16 rows x 7 bits = 112 contiguous floats, coalesced ----
    const unsigned out_base  = base_row * N_OUT;
    const unsigned out_total = (unsigned)nrows * N_OUT;
    #pragma unroll
    for (int k = 0; k < 4; k++) {
        const unsigned e  = k * 32 + lane;
        const unsigned ec = (e < R * N_OUT) ? e : (R * N_OUT - 1);
        const unsigned j  = ec / N_OUT;            // row within the group
        const unsigned b  = ec - j * N_OUT;        // output bit (MSB-first)
        const int idx = __shfl_sync(0xffffffffu, myidx, j);   // uniform control
        const unsigned eg = out_base + e;
        if ((e < R * N_OUT) & (eg < out_total))
            __stcs(out + eg, (float)((idx >> (6 - b)) & 1));
    }
}

extern "C" void kernel_launch(void* const* d_in, const int* in_sizes, int n_in,
                              void* d_out, int out_size)
{
    const float* X = (const float*)d_in[0];
    float* out = (float*)d_out;

    const int nrows = in_sizes[0] / N_BITS;   // 2,000,000

    const int warps_needed    = (nrows + R - 1) / R;
    const int threads         = 256;          // 8 warps per block
    const int warps_per_block = threads / 32;
    const int blocks = (warps_needed + warps_per_block - 1) / warps_per_block;

    lzd108_kernel<<<blocks, threads>>>(X, out, nrows);
}